// round 9
// baseline (speedup 1.0000x reference)
#include <cuda_runtime.h>
#include <math.h>
#include <stdint.h>

#define NB 2
#define NN 384
#define DD 128
#define NSQ (NN*NN)
#define ROWS_E (NB*NSQ)
#define ROWS_N (NB*NN)
#define T128 (ROWS_E/128)    // 2304
#define SCALE 0.08838834764831845f

__device__ __align__(256) float g_qkvn[ROWS_N*384];
__device__ __align__(256) float g_qkve[(size_t)ROWS_E*512];
__device__ __align__(256) float g_attn[ROWS_N*DD];
__device__ __align__(256) float g_mJ[ROWS_N*DD];
__device__ __align__(256) float g_mI[ROWS_N*DD];
__device__ __align__(256) float g_P[ROWS_N*DD];
__device__ __align__(256) float g_Q[ROWS_N*DD];
__device__ __align__(256) float g_buf[(size_t)ROWS_E*DD];
__device__ __align__(256) float g_h[(size_t)ROWS_E*256];

__device__ __forceinline__ float geluf(float x){return 0.5f*x*(1.f+erff(x*0.70710678118654752f));}
__device__ __forceinline__ float wsum(float v){
    #pragma unroll
    for(int o=16;o;o>>=1)v+=__shfl_xor_sync(0xffffffffu,v,o);return v;}
__device__ __forceinline__ float wmax(float v){
    #pragma unroll
    for(int o=16;o;o>>=1)v=fmaxf(v,__shfl_xor_sync(0xffffffffu,v,o));return v;}

__device__ __forceinline__ uint32_t smem_u32(const void* p){
    uint32_t a;asm("{ .reg .u64 t; cvta.to.shared.u64 t, %1; cvt.u32.u64 %0, t; }":"=r"(a):"l"(p));return a;}
__device__ __forceinline__ void split2(float a,float b,uint32_t&h,uint32_t&l){
    asm("cvt.rn.bf16x2.f32 %0,%1,%2;":"=r"(h):"f"(b),"f"(a));
    float ha=__uint_as_float(h<<16),hb=__uint_as_float(h&0xffff0000u);
    float la=a-ha,lb=b-hb;
    asm("cvt.rn.bf16x2.f32 %0,%1,%2;":"=r"(l):"f"(lb),"f"(la));}
__device__ __forceinline__ void ldsm4(uint32_t&r0,uint32_t&r1,uint32_t&r2,uint32_t&r3,uint32_t a){
    asm volatile("ldmatrix.sync.aligned.m8n8.x4.shared.b16 {%0,%1,%2,%3},[%4];"
        :"=r"(r0),"=r"(r1),"=r"(r2),"=r"(r3):"r"(a));}
__device__ __forceinline__ void mma16816(float* d,const uint32_t* a,uint32_t b0,uint32_t b1){
    asm volatile("mma.sync.aligned.m16n8k16.row.col.f32.bf16.bf16.f32 "
        "{%0,%1,%2,%3},{%4,%5,%6,%7},{%8,%9},{%0,%1,%2,%3};"
        :"+f"(d[0]),"+f"(d[1]),"+f"(d[2]),"+f"(d[3])
        :"r"(a[0]),"r"(a[1]),"r"(a[2]),"r"(a[3]),"r"(b0),"r"(b1));}

// convert one 128x128 fp32 tile -> hi/lo bf16 smem (256B rows, 16B-chunk XOR swizzle)
// 512 threads: 4 threads per row, 8 float4 chunks each
template<bool TRANS>
__device__ __forceinline__ void convA(const float* __restrict__ A,int a_s4,int a_c4,
                                      size_t t,char* hi,char* lo,int tid){
    size_t r0=t*128;
    int m=tid>>2,qt=tid&3;
    const float4* src;
    if(TRANS){
        int bb=(int)(r0/NSQ),rem=(int)(r0%NSQ),iI=rem/NN,j0=rem%NN;
        src=(const float4*)A+((size_t)(bb*NN+(j0+m))*NN+iI)*32+qt*8;
    }else{
        src=(const float4*)A+(r0+m)*(size_t)a_s4+a_c4+qt*8;
    }
    char* rh=hi+m*256;char* rl=lo+m*256;
    int x7=m&7;
    #pragma unroll
    for(int i=0;i<8;i++){
        float4 x=__ldg(src+i);
        uint32_t h0,l0,h1,l1;
        split2(x.x,x.y,h0,l0);split2(x.z,x.w,h1,l1);
        int ig=qt*8+i;
        int kp0=ig*2,kp1=ig*2+1;
        uint32_t s0=(uint32_t)((((kp0>>2)^x7)<<4)+((kp0&3)<<2));
        uint32_t s1=(uint32_t)((((kp1>>2)^x7)<<4)+((kp1&3)<<2));
        *(uint32_t*)(rh+s0)=h0;*(uint32_t*)(rh+s1)=h1;
        *(uint32_t*)(rl+s0)=l0;*(uint32_t*)(rl+s1)=l1;
    }
}

// MODE: 0=RAW, 1=E1 gelu(c+bias+add1+P[i]+Q[j]) (P via lng, Q via lnb),
//       2=LN(c+bias+add1), 3=GELU(c), 4=LN(c+bias+add1+out_inplace)
template<int MODE,bool TRANS>
__global__ __launch_bounds__(512,1) void k_mm(
    const float* __restrict__ A,int a_s4,int a_c4,
    const float* __restrict__ W,int w_ld,int w_cf,
    float* __restrict__ out,int o_st,int o_cf,
    const float* __restrict__ add1,const float* __restrict__ bias,
    const float* __restrict__ lng,const float* __restrict__ lnb)
{
    extern __shared__ char dyn[];
    char* base=(char*)((((uintptr_t)dyn)+1023)&~(uintptr_t)1023);
    char* Ah=base;char* Al=base+32768;
    char* Wh=base+65536;char* Wl=base+98304;
    float* stage=(float*)(base+131072);   // 128 x 132 f32
    int tid=threadIdx.x,wp=tid>>5,lane=tid&31;
    int wr=wp>>2,wc=wp&3;                 // 4x4 warp grid, 32x32 per warp
    int l15=lane&15,kh=lane>>4,x7=l15&7;

    // ---- weights: Wt[n][k]=W[k][w_cf+n], hi/lo swizzled (512 thr: 4 k-quarters) ----
    {
        int n=tid&127,kq=(tid>>7)*32;
        char* rh=Wh+n*256;char* rl=Wl+n*256;
        int nx7=n&7;
        #pragma unroll
        for(int kk=0;kk<32;kk+=2){
            int k=kq+kk;
            float w0=__ldg(W+(size_t)k*w_ld+w_cf+n);
            float w1=__ldg(W+(size_t)(k+1)*w_ld+w_cf+n);
            uint32_t h2,l2;split2(w0,w1,h2,l2);
            int kp=k>>1;
            uint32_t s=(uint32_t)((((kp>>2)^nx7)<<4)+((kp&3)<<2));
            *(uint32_t*)(rh+s)=h2;*(uint32_t*)(rl+s)=l2;
        }
    }
    size_t t=blockIdx.x;
    if(t<T128)convA<TRANS>(A,a_s4,a_c4,t,Ah,Al,tid);
    __syncthreads();
    uint32_t AhU=smem_u32(Ah),AlU=smem_u32(Al),WhU=smem_u32(Wh),WlU=smem_u32(Wl);
    uint32_t rowA0=(uint32_t)(wr*32+l15)*256,rowA1=(uint32_t)(wr*32+16+l15)*256;
    uint32_t rowB0=(uint32_t)(wc*32+l15)*256,rowB1=(uint32_t)(wc*32+16+l15)*256;

    for(;t<T128;t+=gridDim.x){
        float acc[2][4][4];
        #pragma unroll
        for(int mi=0;mi<2;mi++)
            #pragma unroll
            for(int ni=0;ni<4;ni++){acc[mi][ni][0]=0.f;acc[mi][ni][1]=0.f;acc[mi][ni][2]=0.f;acc[mi][ni][3]=0.f;}
        #pragma unroll 2
        for(int ks=0;ks<8;ks++){
            uint32_t coff=(uint32_t)(((ks*2+kh)^x7)<<4);
            uint32_t ah[2][4],al[2][4];
            ldsm4(ah[0][0],ah[0][1],ah[0][2],ah[0][3],AhU+rowA0+coff);
            ldsm4(ah[1][0],ah[1][1],ah[1][2],ah[1][3],AhU+rowA1+coff);
            ldsm4(al[0][0],al[0][1],al[0][2],al[0][3],AlU+rowA0+coff);
            ldsm4(al[1][0],al[1][1],al[1][2],al[1][3],AlU+rowA1+coff);
            uint32_t bh0,bh1,bh2,bh3,bl0,bl1,bl2,bl3;
            ldsm4(bh0,bh1,bh2,bh3,WhU+rowB0+coff);
            ldsm4(bl0,bl1,bl2,bl3,WlU+rowB0+coff);
            #pragma unroll
            for(int mi=0;mi<2;mi++){
                mma16816(acc[mi][0],ah[mi],bh0,bh2);
                mma16816(acc[mi][0],al[mi],bh0,bh2);
                mma16816(acc[mi][0],ah[mi],bl0,bl2);
                mma16816(acc[mi][1],ah[mi],bh1,bh3);
                mma16816(acc[mi][1],al[mi],bh1,bh3);
                mma16816(acc[mi][1],ah[mi],bl1,bl3);
            }
            ldsm4(bh0,bh1,bh2,bh3,WhU+rowB1+coff);
            ldsm4(bl0,bl1,bl2,bl3,WlU+rowB1+coff);
            #pragma unroll
            for(int mi=0;mi<2;mi++){
                mma16816(acc[mi][2],ah[mi],bh0,bh2);
                mma16816(acc[mi][2],al[mi],bh0,bh2);
                mma16816(acc[mi][2],ah[mi],bl0,bl2);
                mma16816(acc[mi][3],ah[mi],bh1,bh3);
                mma16816(acc[mi][3],al[mi],bh1,bh3);
                mma16816(acc[mi][3],ah[mi],bl1,bl3);
            }
        }
        // stage accumulators
        #pragma unroll
        for(int mi=0;mi<2;mi++){
            int row=wr*32+mi*16+(lane>>2);
            #pragma unroll
            for(int ni=0;ni<4;ni++){
                int col=wc*32+ni*8+(lane&3)*2;
                *(float2*)&stage[row*132+col]=make_float2(acc[mi][ni][0],acc[mi][ni][1]);
                *(float2*)&stage[(row+8)*132+col]=make_float2(acc[mi][ni][2],acc[mi][ni][3]);
            }
        }
        __syncthreads();
        size_t tn=t+gridDim.x;
        if(tn<T128)convA<TRANS>(A,a_s4,a_c4,tn,Ah,Al,tid);
        // ---- epilogue: 4 threads per row, 32 cols each ----
        {
            size_t r0=t*128;
            int m=tid>>2,qt=tid&3;
            size_t row=r0+m;
            const float* srow=stage+m*132+qt*32;
            float* orow=out+row*(size_t)o_st+o_cf+qt*32;
            if constexpr(MODE==0){
                #pragma unroll
                for(int n=0;n<32;n+=4)*(float4*)(orow+n)=*(const float4*)(srow+n);
            }else if constexpr(MODE==3){
                #pragma unroll
                for(int n=0;n<32;n+=4){
                    float4 c=*(const float4*)(srow+n);
                    *(float4*)(orow+n)=make_float4(geluf(c.x),geluf(c.y),geluf(c.z),geluf(c.w));
                }
            }else if constexpr(MODE==1){
                int bb=(int)(r0/NSQ),rem=(int)(r0%NSQ),iI=rem/NN,j=rem%NN+m;
                const float* Pr=lng+(size_t)(bb*NN+iI)*128+qt*32;
                const float* Qr=lnb+(size_t)(bb*NN+j)*128+qt*32;
                const float* a1=add1+row*128+qt*32;
                const float* bi=bias+qt*32;
                #pragma unroll
                for(int n=0;n<32;n+=4){
                    float4 c=*(const float4*)(srow+n);
                    float4 p4=*(const float4*)(Pr+n),q4=*(const float4*)(Qr+n);
                    float4 a4=*(const float4*)(a1+n),b4=*(const float4*)(bi+n);
                    float4 o;
                    o.x=geluf(c.x+b4.x+p4.x+q4.x+a4.x);
                    o.y=geluf(c.y+b4.y+p4.y+q4.y+a4.y);
                    o.z=geluf(c.z+b4.z+p4.z+q4.z+a4.z);
                    o.w=geluf(c.w+b4.w+p4.w+q4.w+a4.w);
                    *(float4*)(orow+n)=o;
                }
            }else{
                const float* a1=add1+row*128+qt*32;
                const float* bi=bias+qt*32;
                float v[32];
                float s=0.f;
                #pragma unroll
                for(int n=0;n<32;n+=4){
                    float4 c=*(const float4*)(srow+n);
                    float4 a4=*(const float4*)(a1+n),b4=*(const float4*)(bi+n);
                    v[n]=c.x+b4.x+a4.x;v[n+1]=c.y+b4.y+a4.y;
                    v[n+2]=c.z+b4.z+a4.z;v[n+3]=c.w+b4.w+a4.w;
                    if constexpr(MODE==4){
                        float4 t4=*(const float4*)(orow+n);
                        v[n]+=t4.x;v[n+1]+=t4.y;v[n+2]+=t4.z;v[n+3]+=t4.w;
                    }
                    s+=v[n]+v[n+1]+v[n+2]+v[n+3];
                }
                s+=__shfl_xor_sync(0xffffffffu,s,1);
                s+=__shfl_xor_sync(0xffffffffu,s,2);
                float mean=s*(1.f/128.f),s2=0.f;
                #pragma unroll
                for(int n=0;n<32;n++){v[n]-=mean;s2+=v[n]*v[n];}
                s2+=__shfl_xor_sync(0xffffffffu,s2,1);
                s2+=__shfl_xor_sync(0xffffffffu,s2,2);
                float rs=rsqrtf(s2*(1.f/128.f)+1e-5f);
                const float* gg=lng+qt*32;const float* bb2=lnb+qt*32;
                #pragma unroll
                for(int n=0;n<32;n+=4){
                    float4 g4=*(const float4*)(gg+n),b4=*(const float4*)(bb2+n);
                    float4 o;
                    o.x=v[n]*rs*g4.x+b4.x;o.y=v[n+1]*rs*g4.y+b4.y;
                    o.z=v[n+2]*rs*g4.z+b4.z;o.w=v[n+3]*rs*g4.w+b4.w;
                    *(float4*)(orow+n)=o;
                }
            }
        }
        __syncthreads();
    }
}

// ===================== small fp32 kernels =====================
__global__ __launch_bounds__(384) void k_qkvn(const float* __restrict__ node,const float* __restrict__ W){
    int row=blockIdx.x,c=threadIdx.x;
    __shared__ float s[DD];
    if(c<DD)s[c]=node[row*DD+c];
    __syncthreads();
    float a=0.f;
    #pragma unroll 8
    for(int k=0;k<DD;k++)a+=s[k]*W[k*384+c];
    g_qkvn[row*384+c]=a;
}

__global__ __launch_bounds__(128) void k_attn(){
    int w=threadIdx.x>>5,lane=threadIdx.x&31;
    int gw=blockIdx.x*4+w;
    int b=gw/(8*NN),rr=gw%(8*NN),h=rr/NN,i=rr%NN;
    const float* qb=g_qkvn+(b*NN+i)*384+h*48;
    float qv[16];
    #pragma unroll
    for(int c=0;c<16;c++)qv[c]=qb[c];
    const float* eb=g_qkve+((size_t)(b*NN+i)*NN)*512+h*64;
    float dl[12];
    #pragma unroll
    for(int t=0;t<12;t++){
        int j=lane+32*t;
        const float4* e4=(const float4*)(eb+(size_t)j*512);
        const float4* k4=(const float4*)(g_qkvn+(b*NN+j)*384+h*48+16);
        float d=0.f;
        #pragma unroll
        for(int q=0;q<4;q++){
            float4 eq=e4[q],ek=e4[4+q],kk=k4[q];
            d+=(qv[4*q]+eq.x)*(kk.x+ek.x)+(qv[4*q+1]+eq.y)*(kk.y+ek.y)
              +(qv[4*q+2]+eq.z)*(kk.z+ek.z)+(qv[4*q+3]+eq.w)*(kk.w+ek.w);
        }
        dl[t]=d*SCALE;
    }
    float m=dl[0];
    #pragma unroll
    for(int t=1;t<12;t++)m=fmaxf(m,dl[t]);
    m=wmax(m);
    float s=0.f,out[16];
    #pragma unroll
    for(int c=0;c<16;c++)out[c]=0.f;
    #pragma unroll
    for(int t=0;t<12;t++){
        int j=lane+32*t;
        float p=__expf(dl[t]-m);s+=p;
        const float4* e4=(const float4*)(eb+(size_t)j*512);
        const float4* v4=(const float4*)(g_qkvn+(b*NN+j)*384+h*48+32);
        #pragma unroll
        for(int q=0;q<4;q++){
            float4 ev=e4[8+q],em=e4[12+q],vn=v4[q];
            out[4*q]+=p*(vn.x*em.x+ev.x);out[4*q+1]+=p*(vn.y*em.y+ev.y);
            out[4*q+2]+=p*(vn.z*em.z+ev.z);out[4*q+3]+=p*(vn.w*em.w+ev.w);
        }
    }
    s=wsum(s);
    float inv=1.f/s;
    #pragma unroll
    for(int c=0;c<16;c++){
        float v=wsum(out[c]);
        if(lane==0)g_attn[(b*NN+i)*DD+h*16+c]=v*inv;
    }
}

__global__ __launch_bounds__(128) void k_node(const float* __restrict__ node,const float* __restrict__ w0,const float* __restrict__ b0,
    const float* __restrict__ g0,const float* __restrict__ be0,const float* __restrict__ g1,const float* __restrict__ be1,
    const float* __restrict__ w1,const float* __restrict__ w2,const float* __restrict__ b2,float* __restrict__ x){
    int row=blockIdx.x,c=threadIdx.x;
    __shared__ float sa[DD],sx[DD],sh[256],sr[8];
    sa[c]=g_attn[row*DD+c];
    __syncthreads();
    float y=b0[c];
    #pragma unroll 4
    for(int k=0;k<DD;k++)y+=sa[k]*w0[k*DD+c];
    float r=node[row*DD+c]+y;
    float t=wsum(r);if((c&31)==0)sr[c>>5]=t;__syncthreads();
    float mean=(sr[0]+sr[1]+sr[2]+sr[3])*(1.f/DD);
    float d=r-mean;
    t=wsum(d*d);if((c&31)==0)sr[4+(c>>5)]=t;__syncthreads();
    float x0=d*rsqrtf((sr[4]+sr[5]+sr[6]+sr[7])*(1.f/DD)+1e-5f)*g0[c]+be0[c];
    sx[c]=x0;__syncthreads();
    float h0=0.f,h1=0.f;
    #pragma unroll 4
    for(int k=0;k<DD;k++){float v=sx[k];h0+=v*w1[k*256+c];h1+=v*w1[k*256+c+128];}
    sh[c]=geluf(h0);sh[c+128]=geluf(h1);
    __syncthreads();
    float z=b2[c];
    #pragma unroll 4
    for(int k=0;k<256;k++)z+=sh[k]*w2[k*DD+c];
    float r2=x0+z;
    __syncthreads();
    t=wsum(r2);if((c&31)==0)sr[c>>5]=t;__syncthreads();
    float m2=(sr[0]+sr[1]+sr[2]+sr[3])*(1.f/DD);
    float d2=r2-m2;
    t=wsum(d2*d2);if((c&31)==0)sr[4+(c>>5)]=t;__syncthreads();
    x[row*DD+c]=d2*rsqrtf((sr[4]+sr[5]+sr[6]+sr[7])*(1.f/DD)+1e-5f)*g1[c]+be1[c];
}

__global__ __launch_bounds__(128) void k_means(const float* __restrict__ edge){
    int bi=blockIdx.x,c=threadIdx.x,b=bi/NN,r=bi%NN;
    float s=0.f;
    if(blockIdx.y==0){
        const float* p=edge+((size_t)(b*NN+r)*NN)*DD+c;
        for(int j=0;j<NN;j++)s+=p[(size_t)j*DD];
        g_mJ[bi*DD+c]=s*(1.f/NN);
    }else{
        const float* p=edge+((size_t)b*NSQ+r)*DD+c;
        for(int i=0;i<NN;i++)s+=p[(size_t)i*NN*DD];
        g_mI[bi*DD+c]=s*(1.f/NN);
    }
}

__global__ __launch_bounds__(128) void k_PQ(const float* __restrict__ x,const float* __restrict__ ws,const float* __restrict__ bs,
    const float* __restrict__ wt,const float* __restrict__ bt,const float* __restrict__ wer,const float* __restrict__ wec){
    int bi=blockIdx.x,c=threadIdx.x;
    __shared__ float sx[DD],sj[DD],si[DD];
    sx[c]=x[bi*DD+c];sj[c]=g_mJ[bi*DD+c];si[c]=g_mI[bi*DD+c];
    __syncthreads();
    float P=bs[c],Q=bt[c];
    #pragma unroll 4
    for(int k=0;k<DD;k++){
        P+=sx[k]*ws[k*DD+c]+sj[k]*wer[k*DD+c];
        Q+=sx[k]*wt[k*DD+c]+si[k]*wec[k*DD+c];
    }
    g_P[bi*DD+c]=P;g_Q[bi*DD+c]=Q;
}

extern "C" void kernel_launch(void* const* d_in,const int* in_sizes,int n_in,void* d_out,int out_size){
    const float* node=(const float*)d_in[0];
    const float* edge=(const float*)d_in[1];
    const float* wqkvn=(const float*)d_in[3];
    const float* wqkve=(const float*)d_in[4];
    const float* lin0w=(const float*)d_in[5];
    const float* lin0b=(const float*)d_in[6];
    const float* ln0g=(const float*)d_in[7];
    const float* ln0b=(const float*)d_in[8];
    const float* ln1g=(const float*)d_in[9];
    const float* ln1b=(const float*)d_in[10];
    const float* w1=(const float*)d_in[11];
    const float* w2=(const float*)d_in[12];
    const float* b2=(const float*)d_in[13];
    const float* e0we=(const float*)d_in[14];
    const float* e0be=(const float*)d_in[15];
    const float* e0ws=(const float*)d_in[16];
    const float* e0bs=(const float*)d_in[17];
    const float* e0wt=(const float*)d_in[18];
    const float* e0bt=(const float*)d_in[19];
    const float* e0wer=(const float*)d_in[20];
    const float* e0wec=(const float*)d_in[21];
    const float* e0w1=(const float*)d_in[22];
    const float* e0b1=(const float*)d_in[23];
    const float* e1w1=(const float*)d_in[24];
    const float* e1w2=(const float*)d_in[25];
    const float* e1b2=(const float*)d_in[26];
    const float* eln0g=(const float*)d_in[27];
    const float* eln0b=(const float*)d_in[28];
    const float* eln1g=(const float*)d_in[29];
    const float* eln1b=(const float*)d_in[30];
    float* xout=(float*)d_out;
    float* eout=(float*)d_out+(size_t)ROWS_N*DD;

    const int SMTC=131072+132*128*4+1024;   // 199680
    cudaFuncSetAttribute(k_mm<0,false>,cudaFuncAttributeMaxDynamicSharedMemorySize,SMTC);
    cudaFuncSetAttribute(k_mm<1,true >,cudaFuncAttributeMaxDynamicSharedMemorySize,SMTC);
    cudaFuncSetAttribute(k_mm<2,false>,cudaFuncAttributeMaxDynamicSharedMemorySize,SMTC);
    cudaFuncSetAttribute(k_mm<3,false>,cudaFuncAttributeMaxDynamicSharedMemorySize,SMTC);
    cudaFuncSetAttribute(k_mm<4,false>,cudaFuncAttributeMaxDynamicSharedMemorySize,SMTC);

    float *gq,*gh,*gb,*gp,*gqq;
    cudaGetSymbolAddress((void**)&gq,g_qkve);
    cudaGetSymbolAddress((void**)&gh,g_h);
    cudaGetSymbolAddress((void**)&gb,g_buf);
    cudaGetSymbolAddress((void**)&gp,g_P);
    cudaGetSymbolAddress((void**)&gqq,g_Q);

    k_qkvn<<<ROWS_N,384>>>(node,wqkvn);
    for(int q=0;q<4;q++)
        k_mm<0,false><<<148,512,SMTC>>>(edge,32,0, wqkve,512,q*128, gq,512,q*128, nullptr,nullptr,nullptr,nullptr);
    k_means<<<dim3(ROWS_N,2),128>>>(edge);
    k_attn<<<ROWS_N*8/4,128>>>();
    k_node<<<ROWS_N,128>>>(node,lin0w,lin0b,ln0g,ln0b,ln1g,ln1b,w1,w2,b2,xout);
    k_PQ<<<ROWS_N,128>>>(xout,e0ws,e0bs,e0wt,e0bt,e0wer,e0wec);
    // e1 pass1: edge @ We[0:128] -> scratch gh (stride 128)
    k_mm<0,false><<<148,512,SMTC>>>(edge,32,0, e0we,128,0, gh,128,0, nullptr,nullptr,nullptr,nullptr);
    // e1 pass2: edgeT @ We[128:256] + scratch + be + P + Q -> gelu -> g_buf
    k_mm<1,true ><<<148,512,SMTC>>>(edge,32,0, e0we+(size_t)128*128,128,0, gb,128,0, gh,e0be,gp,gqq);
    // e2: LN(edge + g_buf@W1 + b1) -> eout
    k_mm<2,false><<<148,512,SMTC>>>(gb,32,0, e0w1,128,0, eout,128,0, edge,e0b1,eln0g,eln0b);
    // e3: h = gelu(eout @ e1w1) halves -> gh (stride 256)
    for(int hf=0;hf<2;hf++)
        k_mm<3,false><<<148,512,SMTC>>>(eout,32,0, e1w1,256,hf*128, gh,256,hf*128, nullptr,nullptr,nullptr,nullptr);
    // e4 pass1: h[:,0:128] @ W2[0:128] -> g_buf scratch
    k_mm<0,false><<<148,512,SMTC>>>(gh,64,0, e1w2,128,0, gb,128,0, nullptr,nullptr,nullptr,nullptr);
    // e4 pass2: LN(eout + scratch + h[:,128:256]@W2[128:256] + b2) -> eout
    k_mm<4,false><<<148,512,SMTC>>>(gh,64,32, e1w2+(size_t)128*128,128,0, eout,128,0, gb,e1b2,eln1g,eln1b);
}

// round 10
// speedup vs baseline: 1.2965x; 1.2965x over previous
#include <cuda_runtime.h>
#include <math.h>
#include <stdint.h>

#define NB 2
#define NN 384
#define DD 128
#define NSQ (NN*NN)
#define ROWS_E (NB*NSQ)
#define ROWS_N (NB*NN)
#define T128 (ROWS_E/128)    // 2304
#define SCALE 0.08838834764831845f

__device__ __align__(256) float g_qkvn[ROWS_N*384];
__device__ __align__(256) float g_qkve[(size_t)ROWS_E*512];
__device__ __align__(256) float g_attn[ROWS_N*DD];
__device__ __align__(256) float g_mJ[ROWS_N*DD];
__device__ __align__(256) float g_mI[ROWS_N*DD];
__device__ __align__(256) float g_P[ROWS_N*DD];
__device__ __align__(256) float g_Q[ROWS_N*DD];
__device__ __align__(256) float g_buf[(size_t)ROWS_E*DD];
__device__ __align__(256) float g_h[(size_t)ROWS_E*256];

__device__ __forceinline__ float geluf(float x){return 0.5f*x*(1.f+erff(x*0.70710678118654752f));}
__device__ __forceinline__ float wsum(float v){
    #pragma unroll
    for(int o=16;o;o>>=1)v+=__shfl_xor_sync(0xffffffffu,v,o);return v;}
__device__ __forceinline__ float wmax(float v){
    #pragma unroll
    for(int o=16;o;o>>=1)v=fmaxf(v,__shfl_xor_sync(0xffffffffu,v,o));return v;}

__device__ __forceinline__ uint32_t smem_u32(const void* p){
    uint32_t a;asm("{ .reg .u64 t; cvta.to.shared.u64 t, %1; cvt.u32.u64 %0, t; }":"=r"(a):"l"(p));return a;}
__device__ __forceinline__ void split2(float a,float b,uint32_t&h,uint32_t&l){
    asm("cvt.rn.bf16x2.f32 %0,%1,%2;":"=r"(h):"f"(b),"f"(a));
    float ha=__uint_as_float(h<<16),hb=__uint_as_float(h&0xffff0000u);
    float la=a-ha,lb=b-hb;
    asm("cvt.rn.bf16x2.f32 %0,%1,%2;":"=r"(l):"f"(lb),"f"(la));}
__device__ __forceinline__ void ldsm4(uint32_t&r0,uint32_t&r1,uint32_t&r2,uint32_t&r3,uint32_t a){
    asm volatile("ldmatrix.sync.aligned.m8n8.x4.shared.b16 {%0,%1,%2,%3},[%4];"
        :"=r"(r0),"=r"(r1),"=r"(r2),"=r"(r3):"r"(a));}
__device__ __forceinline__ void mma16816(float* d,const uint32_t* a,uint32_t b0,uint32_t b1){
    asm volatile("mma.sync.aligned.m16n8k16.row.col.f32.bf16.bf16.f32 "
        "{%0,%1,%2,%3},{%4,%5,%6,%7},{%8,%9},{%0,%1,%2,%3};"
        :"+f"(d[0]),"+f"(d[1]),"+f"(d[2]),"+f"(d[3])
        :"r"(a[0]),"r"(a[1]),"r"(a[2]),"r"(a[3]),"r"(b0),"r"(b1));}

// convert one 128x128 fp32 tile -> hi/lo bf16 smem (256B rows, 16B-chunk XOR swizzle)
template<bool TRANS>
__device__ __forceinline__ void convA(const float* __restrict__ A,int a_s4,int a_c4,
                                      size_t t,char* hi,char* lo,int tid){
    size_t r0=t*128;
    int m=tid>>2,qt=tid&3;
    const float4* src;
    if(TRANS){
        int bb=(int)(r0/NSQ),rem=(int)(r0%NSQ),iI=rem/NN,j0=rem%NN;
        src=(const float4*)A+((size_t)(bb*NN+(j0+m))*NN+iI)*32+qt*8;
    }else{
        src=(const float4*)A+(r0+m)*(size_t)a_s4+a_c4+qt*8;
    }
    char* rh=hi+m*256;char* rl=lo+m*256;
    int x7=m&7;
    #pragma unroll
    for(int i=0;i<8;i++){
        float4 x=__ldg(src+i);
        uint32_t h0,l0,h1,l1;
        split2(x.x,x.y,h0,l0);split2(x.z,x.w,h1,l1);
        int ig=qt*8+i;
        int kp0=ig*2,kp1=ig*2+1;
        uint32_t s0=(uint32_t)((((kp0>>2)^x7)<<4)+((kp0&3)<<2));
        uint32_t s1=(uint32_t)((((kp1>>2)^x7)<<4)+((kp1&3)<<2));
        *(uint32_t*)(rh+s0)=h0;*(uint32_t*)(rh+s1)=h1;
        *(uint32_t*)(rl+s0)=l0;*(uint32_t*)(rl+s1)=l1;
    }
}

// ===================== unfused GEMM (N=128) =====================
// MODE: 0=RAW(direct), 1=E1 gelu(c+bias+add1+P[i]+Q[j]) direct (P via lng, Q via lnb),
//       2=LN(c+bias+add1) staged, 3=GELU direct, 4=LN(c+bias+add1+out) staged
template<int MODE,bool TRANS>
__global__ __launch_bounds__(512,1) void k_mm(
    const float* __restrict__ A,int a_s4,int a_c4,
    const float* __restrict__ W,int w_ld,int w_cf,
    float* __restrict__ out,int o_st,int o_cf,
    const float* __restrict__ add1,const float* __restrict__ bias,
    const float* __restrict__ lng,const float* __restrict__ lnb)
{
    extern __shared__ char dyn[];
    char* base=(char*)((((uintptr_t)dyn)+1023)&~(uintptr_t)1023);
    char* Ah=base;char* Al=base+32768;
    char* Wh=base+65536;char* Wl=base+98304;
    float* stage=(float*)(base+131072);
    int tid=threadIdx.x,wp=tid>>5,lane=tid&31;
    int wr=wp>>2,wc=wp&3;
    int l15=lane&15,kh=lane>>4,x7=l15&7;

    {   // weights
        int n=tid&127,kq=(tid>>7)*32;
        char* rh=Wh+n*256;char* rl=Wl+n*256;
        int nx7=n&7;
        #pragma unroll
        for(int kk=0;kk<32;kk+=2){
            int k=kq+kk;
            float w0=__ldg(W+(size_t)k*w_ld+w_cf+n);
            float w1=__ldg(W+(size_t)(k+1)*w_ld+w_cf+n);
            uint32_t h2,l2;split2(w0,w1,h2,l2);
            int kp=k>>1;
            uint32_t s=(uint32_t)((((kp>>2)^nx7)<<4)+((kp&3)<<2));
            *(uint32_t*)(rh+s)=h2;*(uint32_t*)(rl+s)=l2;
        }
    }
    size_t t=blockIdx.x;
    if(t<T128)convA<TRANS>(A,a_s4,a_c4,t,Ah,Al,tid);
    __syncthreads();
    uint32_t AhU=smem_u32(Ah),AlU=smem_u32(Al),WhU=smem_u32(Wh),WlU=smem_u32(Wl);
    uint32_t rowA0=(uint32_t)(wr*32+l15)*256,rowA1=(uint32_t)(wr*32+16+l15)*256;
    uint32_t rowB0=(uint32_t)(wc*32+l15)*256,rowB1=(uint32_t)(wc*32+16+l15)*256;

    for(;t<T128;t+=gridDim.x){
        float acc[2][4][4];
        #pragma unroll
        for(int mi=0;mi<2;mi++)
            #pragma unroll
            for(int ni=0;ni<4;ni++){acc[mi][ni][0]=0.f;acc[mi][ni][1]=0.f;acc[mi][ni][2]=0.f;acc[mi][ni][3]=0.f;}
        #pragma unroll 2
        for(int ks=0;ks<8;ks++){
            uint32_t coff=(uint32_t)(((ks*2+kh)^x7)<<4);
            uint32_t ah[2][4],al[2][4];
            ldsm4(ah[0][0],ah[0][1],ah[0][2],ah[0][3],AhU+rowA0+coff);
            ldsm4(ah[1][0],ah[1][1],ah[1][2],ah[1][3],AhU+rowA1+coff);
            ldsm4(al[0][0],al[0][1],al[0][2],al[0][3],AlU+rowA0+coff);
            ldsm4(al[1][0],al[1][1],al[1][2],al[1][3],AlU+rowA1+coff);
            uint32_t bh0,bh1,bh2,bh3,bl0,bl1,bl2,bl3;
            ldsm4(bh0,bh1,bh2,bh3,WhU+rowB0+coff);
            ldsm4(bl0,bl1,bl2,bl3,WlU+rowB0+coff);
            #pragma unroll
            for(int mi=0;mi<2;mi++){
                mma16816(acc[mi][0],ah[mi],bh0,bh2);
                mma16816(acc[mi][0],al[mi],bh0,bh2);
                mma16816(acc[mi][0],ah[mi],bl0,bl2);
                mma16816(acc[mi][1],ah[mi],bh1,bh3);
                mma16816(acc[mi][1],al[mi],bh1,bh3);
                mma16816(acc[mi][1],ah[mi],bl1,bl3);
            }
            ldsm4(bh0,bh1,bh2,bh3,WhU+rowB1+coff);
            ldsm4(bl0,bl1,bl2,bl3,WlU+rowB1+coff);
            #pragma unroll
            for(int mi=0;mi<2;mi++){
                mma16816(acc[mi][2],ah[mi],bh0,bh2);
                mma16816(acc[mi][2],al[mi],bh0,bh2);
                mma16816(acc[mi][2],ah[mi],bl0,bl2);
                mma16816(acc[mi][3],ah[mi],bh1,bh3);
                mma16816(acc[mi][3],al[mi],bh1,bh3);
                mma16816(acc[mi][3],ah[mi],bl1,bl3);
            }
        }
        size_t r0=t*128;
        if constexpr(MODE==2||MODE==4){
            #pragma unroll
            for(int mi=0;mi<2;mi++){
                int row=wr*32+mi*16+(lane>>2);
                #pragma unroll
                for(int ni=0;ni<4;ni++){
                    int col=wc*32+ni*8+(lane&3)*2;
                    *(float2*)&stage[row*132+col]=make_float2(acc[mi][ni][0],acc[mi][ni][1]);
                    *(float2*)&stage[(row+8)*132+col]=make_float2(acc[mi][ni][2],acc[mi][ni][3]);
                }
            }
        }
        __syncthreads();
        size_t tn=t+gridDim.x;
        if(tn<T128)convA<TRANS>(A,a_s4,a_c4,tn,Ah,Al,tid);
        if constexpr(MODE==0){
            #pragma unroll
            for(int ni=0;ni<4;ni++){
                int col=o_cf+wc*32+ni*8+(lane&3)*2;
                #pragma unroll
                for(int mi=0;mi<2;mi++){
                    int rl=wr*32+mi*16+(lane>>2);
                    *(float2*)(out+((size_t)r0+rl)*o_st+col)=*(float2*)&acc[mi][ni][0];
                    *(float2*)(out+((size_t)r0+rl+8)*o_st+col)=*(float2*)&acc[mi][ni][2];
                }
            }
        }else if constexpr(MODE==3){
            #pragma unroll
            for(int ni=0;ni<4;ni++){
                int col=o_cf+wc*32+ni*8+(lane&3)*2;
                #pragma unroll
                for(int mi=0;mi<2;mi++){
                    int rl=wr*32+mi*16+(lane>>2);
                    float2 o0=make_float2(geluf(acc[mi][ni][0]),geluf(acc[mi][ni][1]));
                    float2 o1=make_float2(geluf(acc[mi][ni][2]),geluf(acc[mi][ni][3]));
                    *(float2*)(out+((size_t)r0+rl)*o_st+col)=o0;
                    *(float2*)(out+((size_t)r0+rl+8)*o_st+col)=o1;
                }
            }
        }else if constexpr(MODE==1){
            int bb=(int)(r0/NSQ),rem=(int)(r0%NSQ),iI=rem/NN,j0=rem%NN;
            const float* Pr=lng+(size_t)(bb*NN+iI)*128;
            #pragma unroll
            for(int ni=0;ni<4;ni++){
                int col=wc*32+ni*8+(lane&3)*2;
                float2 p2=*(const float2*)(Pr+col);
                float2 b2=*(const float2*)(bias+col);
                #pragma unroll
                for(int mi=0;mi<2;mi++){
                    int rl=wr*32+mi*16+(lane>>2);
                    #pragma unroll
                    for(int h=0;h<2;h++){
                        int row=rl+h*8;
                        float2 c=*(float2*)&acc[mi][ni][h*2];
                        float2 q2=*(const float2*)(lnb+((size_t)(bb*NN+j0+row))*128+col);
                        float2 a2=*(const float2*)(add1+((size_t)r0+row)*128+col);
                        float2 o;
                        o.x=geluf(c.x+b2.x+p2.x+q2.x+a2.x);
                        o.y=geluf(c.y+b2.y+p2.y+q2.y+a2.y);
                        *(float2*)(out+((size_t)r0+row)*o_st+o_cf+col)=o;
                    }
                }
            }
        }else{ // 2,4 staged LN
            int m=tid>>2,qt=tid&3;
            size_t row=r0+m;
            const float* srow=stage+m*132+qt*32;
            float* orow=out+row*(size_t)o_st+o_cf+qt*32;
            const float* a1=add1+row*128+qt*32;
            const float* bi=bias+qt*32;
            float v[32];
            float s=0.f;
            #pragma unroll
            for(int n=0;n<32;n+=4){
                float4 c=*(const float4*)(srow+n);
                float4 a4=*(const float4*)(a1+n),b4=*(const float4*)(bi+n);
                v[n]=c.x+b4.x+a4.x;v[n+1]=c.y+b4.y+a4.y;
                v[n+2]=c.z+b4.z+a4.z;v[n+3]=c.w+b4.w+a4.w;
                if constexpr(MODE==4){
                    float4 t4=*(const float4*)(orow+n);
                    v[n]+=t4.x;v[n+1]+=t4.y;v[n+2]+=t4.z;v[n+3]+=t4.w;
                }
                s+=v[n]+v[n+1]+v[n+2]+v[n+3];
            }
            s+=__shfl_xor_sync(0xffffffffu,s,1);
            s+=__shfl_xor_sync(0xffffffffu,s,2);
            float mean=s*(1.f/128.f),s2=0.f;
            #pragma unroll
            for(int n=0;n<32;n++){v[n]-=mean;s2+=v[n]*v[n];}
            s2+=__shfl_xor_sync(0xffffffffu,s2,1);
            s2+=__shfl_xor_sync(0xffffffffu,s2,2);
            float rs=rsqrtf(s2*(1.f/128.f)+1e-5f);
            const float* gg=lng+qt*32;const float* bb2=lnb+qt*32;
            #pragma unroll
            for(int n=0;n<32;n+=4){
                float4 g4=*(const float4*)(gg+n),b4=*(const float4*)(bb2+n);
                float4 o;
                o.x=v[n]*rs*g4.x+b4.x;o.y=v[n+1]*rs*g4.y+b4.y;
                o.z=v[n+2]*rs*g4.z+b4.z;o.w=v[n+3]*rs*g4.w+b4.w;
                *(float4*)(orow+n)=o;
            }
        }
        __syncthreads();
    }
}

// ===================== fused GEMM (N=256, two B sets, direct store) =====================
// MODE: 0=RAW, 3=GELU
template<int MODE>
__global__ __launch_bounds__(512,1) void k_mm2(
    const float* __restrict__ A,int a_s4,
    const float* __restrict__ W,int w_ld,int w_cf,
    float* __restrict__ out,int o_st,int o_cf)
{
    extern __shared__ char dyn[];
    char* base=(char*)((((uintptr_t)dyn)+1023)&~(uintptr_t)1023);
    char* Ah=base;char* Al=base+32768;
    char* Wb[4]={base+65536,base+98304,base+131072,base+163840}; // Wh0,Wl0,Wh1,Wl1
    int tid=threadIdx.x,wp=tid>>5,lane=tid&31;
    int wr=wp>>2,wc=wp&3;
    int l15=lane&15,kh=lane>>4,x7=l15&7;

    {   // weights for two N-128 sets
        int n2=tid&255,nb=n2>>7,n=n2&127,kq=(tid>>8)*64;
        char* rh=Wb[nb*2]+n*256;char* rl=Wb[nb*2+1]+n*256;
        int nx7=n&7;
        #pragma unroll
        for(int kk=0;kk<64;kk+=2){
            int k=kq+kk;
            float w0=__ldg(W+(size_t)k*w_ld+w_cf+nb*128+n);
            float w1=__ldg(W+(size_t)(k+1)*w_ld+w_cf+nb*128+n);
            uint32_t h2,l2;split2(w0,w1,h2,l2);
            int kp=k>>1;
            uint32_t s=(uint32_t)((((kp>>2)^nx7)<<4)+((kp&3)<<2));
            *(uint32_t*)(rh+s)=h2;*(uint32_t*)(rl+s)=l2;
        }
    }
    size_t t=blockIdx.x;
    if(t<T128)convA<false>(A,a_s4,0,t,Ah,Al,tid);
    __syncthreads();
    uint32_t AhU=smem_u32(Ah),AlU=smem_u32(Al);
    uint32_t WhU[2]={smem_u32(Wb[0]),smem_u32(Wb[2])};
    uint32_t WlU[2]={smem_u32(Wb[1]),smem_u32(Wb[3])};
    uint32_t rowA0=(uint32_t)(wr*32+l15)*256,rowA1=(uint32_t)(wr*32+16+l15)*256;
    uint32_t rowB0=(uint32_t)(wc*32+l15)*256,rowB1=(uint32_t)(wc*32+16+l15)*256;

    for(;t<T128;t+=gridDim.x){
        float acc[2][2][4][4];
        #pragma unroll
        for(int nb=0;nb<2;nb++)
            #pragma unroll
            for(int mi=0;mi<2;mi++)
                #pragma unroll
                for(int ni=0;ni<4;ni++){acc[nb][mi][ni][0]=0.f;acc[nb][mi][ni][1]=0.f;acc[nb][mi][ni][2]=0.f;acc[nb][mi][ni][3]=0.f;}
        for(int ks=0;ks<8;ks++){
            uint32_t coff=(uint32_t)(((ks*2+kh)^x7)<<4);
            uint32_t ah[2][4],al[2][4];
            ldsm4(ah[0][0],ah[0][1],ah[0][2],ah[0][3],AhU+rowA0+coff);
            ldsm4(ah[1][0],ah[1][1],ah[1][2],ah[1][3],AhU+rowA1+coff);
            ldsm4(al[0][0],al[0][1],al[0][2],al[0][3],AlU+rowA0+coff);
            ldsm4(al[1][0],al[1][1],al[1][2],al[1][3],AlU+rowA1+coff);
            #pragma unroll
            for(int nb=0;nb<2;nb++){
                uint32_t bh0,bh1,bh2,bh3,bl0,bl1,bl2,bl3;
                ldsm4(bh0,bh1,bh2,bh3,WhU[nb]+rowB0+coff);
                ldsm4(bl0,bl1,bl2,bl3,WlU[nb]+rowB0+coff);
                #pragma unroll
                for(int mi=0;mi<2;mi++){
                    mma16816(acc[nb][mi][0],ah[mi],bh0,bh2);
                    mma16816(acc[nb][mi][0],al[mi],bh0,bh2);
                    mma16816(acc[nb][mi][0],ah[mi],bl0,bl2);
                    mma16816(acc[nb][mi][1],ah[mi],bh1,bh3);
                    mma16816(acc[nb][mi][1],al[mi],bh1,bh3);
                    mma16816(acc[nb][mi][1],ah[mi],bl1,bl3);
                }
                ldsm4(bh0,bh1,bh2,bh3,WhU[nb]+rowB1+coff);
                ldsm4(bl0,bl1,bl2,bl3,WlU[nb]+rowB1+coff);
                #pragma unroll
                for(int mi=0;mi<2;mi++){
                    mma16816(acc[nb][mi][2],ah[mi],bh0,bh2);
                    mma16816(acc[nb][mi][2],al[mi],bh0,bh2);
                    mma16816(acc[nb][mi][2],ah[mi],bl0,bl2);
                    mma16816(acc[nb][mi][3],ah[mi],bh1,bh3);
                    mma16816(acc[nb][mi][3],al[mi],bh1,bh3);
                    mma16816(acc[nb][mi][3],ah[mi],bl1,bl3);
                }
            }
        }
        __syncthreads();
        size_t tn=t+gridDim.x;
        if(tn<T128)convA<false>(A,a_s4,0,tn,Ah,Al,tid);
        size_t r0=t*128;
        #pragma unroll
        for(int nb=0;nb<2;nb++){
            #pragma unroll
            for(int ni=0;ni<4;ni++){
                int col=o_cf+nb*128+wc*32+ni*8+(lane&3)*2;
                #pragma unroll
                for(int mi=0;mi<2;mi++){
                    int rl=wr*32+mi*16+(lane>>2);
                    if constexpr(MODE==0){
                        *(float2*)(out+((size_t)r0+rl)*o_st+col)=*(float2*)&acc[nb][mi][ni][0];
                        *(float2*)(out+((size_t)r0+rl+8)*o_st+col)=*(float2*)&acc[nb][mi][ni][2];
                    }else{
                        float2 o0=make_float2(geluf(acc[nb][mi][ni][0]),geluf(acc[nb][mi][ni][1]));
                        float2 o1=make_float2(geluf(acc[nb][mi][ni][2]),geluf(acc[nb][mi][ni][3]));
                        *(float2*)(out+((size_t)r0+rl)*o_st+col)=o0;
                        *(float2*)(out+((size_t)r0+rl+8)*o_st+col)=o1;
                    }
                }
            }
        }
        __syncthreads();
    }
}

// ===================== small fp32 kernels =====================
__global__ __launch_bounds__(384) void k_qkvn(const float* __restrict__ node,const float* __restrict__ W){
    int row=blockIdx.x,c=threadIdx.x;
    __shared__ float s[DD];
    if(c<DD)s[c]=node[row*DD+c];
    __syncthreads();
    float a=0.f;
    #pragma unroll 8
    for(int k=0;k<DD;k++)a+=s[k]*W[k*384+c];
    g_qkvn[row*384+c]=a;
}

__global__ __launch_bounds__(128) void k_attn(){
    int w=threadIdx.x>>5,lane=threadIdx.x&31;
    int gw=blockIdx.x*4+w;
    int b=gw/(8*NN),rr=gw%(8*NN),h=rr/NN,i=rr%NN;
    const float* qb=g_qkvn+(b*NN+i)*384+h*48;
    float qv[16];
    #pragma unroll
    for(int c=0;c<16;c++)qv[c]=qb[c];
    const float* eb=g_qkve+((size_t)(b*NN+i)*NN)*512+h*64;
    float dl[12];
    #pragma unroll
    for(int t=0;t<12;t++){
        int j=lane+32*t;
        const float4* e4=(const float4*)(eb+(size_t)j*512);
        const float4* k4=(const float4*)(g_qkvn+(b*NN+j)*384+h*48+16);
        float d=0.f;
        #pragma unroll
        for(int q=0;q<4;q++){
            float4 eq=e4[q],ek=e4[4+q],kk=k4[q];
            d+=(qv[4*q]+eq.x)*(kk.x+ek.x)+(qv[4*q+1]+eq.y)*(kk.y+ek.y)
              +(qv[4*q+2]+eq.z)*(kk.z+ek.z)+(qv[4*q+3]+eq.w)*(kk.w+ek.w);
        }
        dl[t]=d*SCALE;
    }
    float m=dl[0];
    #pragma unroll
    for(int t=1;t<12;t++)m=fmaxf(m,dl[t]);
    m=wmax(m);
    float s=0.f,out[16];
    #pragma unroll
    for(int c=0;c<16;c++)out[c]=0.f;
    #pragma unroll
    for(int t=0;t<12;t++){
        int j=lane+32*t;
        float p=__expf(dl[t]-m);s+=p;
        const float4* e4=(const float4*)(eb+(size_t)j*512);
        const float4* v4=(const float4*)(g_qkvn+(b*NN+j)*384+h*48+32);
        #pragma unroll
        for(int q=0;q<4;q++){
            float4 ev=e4[8+q],em=e4[12+q],vn=v4[q];
            out[4*q]+=p*(vn.x*em.x+ev.x);out[4*q+1]+=p*(vn.y*em.y+ev.y);
            out[4*q+2]+=p*(vn.z*em.z+ev.z);out[4*q+3]+=p*(vn.w*em.w+ev.w);
        }
    }
    s=wsum(s);
    float inv=1.f/s;
    #pragma unroll
    for(int c=0;c<16;c++){
        float v=wsum(out[c]);
        if(lane==0)g_attn[(b*NN+i)*DD+h*16+c]=v*inv;
    }
}

__global__ __launch_bounds__(128) void k_node(const float* __restrict__ node,const float* __restrict__ w0,const float* __restrict__ b0,
    const float* __restrict__ g0,const float* __restrict__ be0,const float* __restrict__ g1,const float* __restrict__ be1,
    const float* __restrict__ w1,const float* __restrict__ w2,const float* __restrict__ b2,float* __restrict__ x){
    int row=blockIdx.x,c=threadIdx.x;
    __shared__ float sa[DD],sx[DD],sh[256],sr[8];
    sa[c]=g_attn[row*DD+c];
    __syncthreads();
    float y=b0[c];
    #pragma unroll 4
    for(int k=0;k<DD;k++)y+=sa[k]*w0[k*DD+c];
    float r=node[row*DD+c]+y;
    float t=wsum(r);if((c&31)==0)sr[c>>5]=t;__syncthreads();
    float mean=(sr[0]+sr[1]+sr[2]+sr[3])*(1.f/DD);
    float d=r-mean;
    t=wsum(d*d);if((c&31)==0)sr[4+(c>>5)]=t;__syncthreads();
    float x0=d*rsqrtf((sr[4]+sr[5]+sr[6]+sr[7])*(1.f/DD)+1e-5f)*g0[c]+be0[c];
    sx[c]=x0;__syncthreads();
    float h0=0.f,h1=0.f;
    #pragma unroll 4
    for(int k=0;k<DD;k++){float v=sx[k];h0+=v*w1[k*256+c];h1+=v*w1[k*256+c+128];}
    sh[c]=geluf(h0);sh[c+128]=geluf(h1);
    __syncthreads();
    float z=b2[c];
    #pragma unroll 4
    for(int k=0;k<256;k++)z+=sh[k]*w2[k*DD+c];
    float r2=x0+z;
    __syncthreads();
    t=wsum(r2);if((c&31)==0)sr[c>>5]=t;__syncthreads();
    float m2=(sr[0]+sr[1]+sr[2]+sr[3])*(1.f/DD);
    float d2=r2-m2;
    t=wsum(d2*d2);if((c&31)==0)sr[4+(c>>5)]=t;__syncthreads();
    x[row*DD+c]=d2*rsqrtf((sr[4]+sr[5]+sr[6]+sr[7])*(1.f/DD)+1e-5f)*g1[c]+be1[c];
}

__global__ __launch_bounds__(128) void k_means(const float* __restrict__ edge){
    int bi=blockIdx.x,c=threadIdx.x,b=bi/NN,r=bi%NN;
    float s=0.f;
    if(blockIdx.y==0){
        const float* p=edge+((size_t)(b*NN+r)*NN)*DD+c;
        for(int j=0;j<NN;j++)s+=p[(size_t)j*DD];
        g_mJ[bi*DD+c]=s*(1.f/NN);
    }else{
        const float* p=edge+((size_t)b*NSQ+r)*DD+c;
        for(int i=0;i<NN;i++)s+=p[(size_t)i*NN*DD];
        g_mI[bi*DD+c]=s*(1.f/NN);
    }
}

__global__ __launch_bounds__(128) void k_PQ(const float* __restrict__ x,const float* __restrict__ ws,const float* __restrict__ bs,
    const float* __restrict__ wt,const float* __restrict__ bt,const float* __restrict__ wer,const float* __restrict__ wec){
    int bi=blockIdx.x,c=threadIdx.x;
    __shared__ float sx[DD],sj[DD],si[DD];
    sx[c]=x[bi*DD+c];sj[c]=g_mJ[bi*DD+c];si[c]=g_mI[bi*DD+c];
    __syncthreads();
    float P=bs[c],Q=bt[c];
    #pragma unroll 4
    for(int k=0;k<DD;k++){
        P+=sx[k]*ws[k*DD+c]+sj[k]*wer[k*DD+c];
        Q+=sx[k]*wt[k*DD+c]+si[k]*wec[k*DD+c];
    }
    g_P[bi*DD+c]=P;g_Q[bi*DD+c]=Q;
}

extern "C" void kernel_launch(void* const* d_in,const int* in_sizes,int n_in,void* d_out,int out_size){
    const float* node=(const float*)d_in[0];
    const float* edge=(const float*)d_in[1];
    const float* wqkvn=(const float*)d_in[3];
    const float* wqkve=(const float*)d_in[4];
    const float* lin0w=(const float*)d_in[5];
    const float* lin0b=(const float*)d_in[6];
    const float* ln0g=(const float*)d_in[7];
    const float* ln0b=(const float*)d_in[8];
    const float* ln1g=(const float*)d_in[9];
    const float* ln1b=(const float*)d_in[10];
    const float* w1=(const float*)d_in[11];
    const float* w2=(const float*)d_in[12];
    const float* b2=(const float*)d_in[13];
    const float* e0we=(const float*)d_in[14];
    const float* e0be=(const float*)d_in[15];
    const float* e0ws=(const float*)d_in[16];
    const float* e0bs=(const float*)d_in[17];
    const float* e0wt=(const float*)d_in[18];
    const float* e0bt=(const float*)d_in[19];
    const float* e0wer=(const float*)d_in[20];
    const float* e0wec=(const float*)d_in[21];
    const float* e0w1=(const float*)d_in[22];
    const float* e0b1=(const float*)d_in[23];
    const float* e1w1=(const float*)d_in[24];
    const float* e1w2=(const float*)d_in[25];
    const float* e1b2=(const float*)d_in[26];
    const float* eln0g=(const float*)d_in[27];
    const float* eln0b=(const float*)d_in[28];
    const float* eln1g=(const float*)d_in[29];
    const float* eln1b=(const float*)d_in[30];
    float* xout=(float*)d_out;
    float* eout=(float*)d_out+(size_t)ROWS_N*DD;

    const int SM_SMALL=131072+1024;         // modes 0/1/3
    const int SM_STAGE=131072+132*128*4+1024; // modes 2/4
    const int SM_FUSED=196608+1024;
    cudaFuncSetAttribute(k_mm<0,false>,cudaFuncAttributeMaxDynamicSharedMemorySize,SM_SMALL);
    cudaFuncSetAttribute(k_mm<1,true >,cudaFuncAttributeMaxDynamicSharedMemorySize,SM_SMALL);
    cudaFuncSetAttribute(k_mm<2,false>,cudaFuncAttributeMaxDynamicSharedMemorySize,SM_STAGE);
    cudaFuncSetAttribute(k_mm<4,false>,cudaFuncAttributeMaxDynamicSharedMemorySize,SM_STAGE);
    cudaFuncSetAttribute(k_mm2<0>,cudaFuncAttributeMaxDynamicSharedMemorySize,SM_FUSED);
    cudaFuncSetAttribute(k_mm2<3>,cudaFuncAttributeMaxDynamicSharedMemorySize,SM_FUSED);

    float *gq,*gh,*gb,*gp,*gqq;
    cudaGetSymbolAddress((void**)&gq,g_qkve);
    cudaGetSymbolAddress((void**)&gh,g_h);
    cudaGetSymbolAddress((void**)&gb,g_buf);
    cudaGetSymbolAddress((void**)&gp,g_P);
    cudaGetSymbolAddress((void**)&gqq,g_Q);

    k_qkvn<<<ROWS_N,384>>>(node,wqkvn);
    for(int q=0;q<2;q++)
        k_mm2<0><<<148,512,SM_FUSED>>>(edge,32, wqkve,512,q*256, gq,512,q*256);
    k_means<<<dim3(ROWS_N,2),128>>>(edge);
    k_attn<<<ROWS_N*8/4,128>>>();
    k_node<<<ROWS_N,128>>>(node,lin0w,lin0b,ln0g,ln0b,ln1g,ln1b,w1,w2,b2,xout);
    k_PQ<<<ROWS_N,128>>>(xout,e0ws,e0bs,e0wt,e0bt,e0wer,e0wec);
    // e1 pass1: edge @ We[0:128] -> gh scratch (stride 128)
    k_mm<0,false><<<148,512,SM_SMALL>>>(edge,32,0, e0we,128,0, gh,128,0, nullptr,nullptr,nullptr,nullptr);
    // e1 pass2: edgeT @ We[128:256] + scratch + be + P + Q -> gelu -> g_buf
    k_mm<1,true ><<<148,512,SM_SMALL>>>(edge,32,0, e0we+(size_t)128*128,128,0, gb,128,0, gh,e0be,gp,gqq);
    // e2: LN(edge + g_buf@W1 + b1) -> eout
    k_mm<2,false><<<148,512,SM_STAGE>>>(gb,32,0, e0w1,128,0, eout,128,0, edge,e0b1,eln0g,eln0b);
    // e3 fused: h = gelu(eout @ e1w1), N=256 -> gh (stride 256)
    k_mm2<3><<<148,512,SM_FUSED>>>(eout,32, e1w1,256,0, gh,256,0);
    // e4 pass1: h[:,0:128] @ W2[0:128] -> g_buf scratch
    k_mm<0,false><<<148,512,SM_SMALL>>>(gh,64,0, e1w2,128,0, gb,128,0, nullptr,nullptr,nullptr,nullptr);
    // e4 pass2: LN(eout + scratch + h[:,128:256]@W2[128:256] + b2) -> eout
    k_mm<4,false><<<148,512,SM_STAGE>>>(gh,64,32, e1w2+(size_t)128*128,128,0, eout,128,0, gb,e1b2,eln1g,eln1b);
}